// round 15
// baseline (speedup 1.0000x reference)
#include <cuda_runtime.h>
#include <cuda_bf16.h>
#include <cuda_fp16.h>
#include <math.h>
#include <stdint.h>

// Problem constants
#define BB 4
#define TT 2048
#define CC 1024
#define HH 16
#define DD 64
#define MROWS (BB * TT)   // 8192
#define QSC (0.125f * 1.44269504088896f)   // 1/sqrt(D) * log2(e), folded into Q

// ---------------------------------------------------------------------------
// Scratch (device globals)
// ---------------------------------------------------------------------------
__device__ __half g_x[MROWS * CC];                        // x fp16 [M,K]
__device__ __half g_wa[3 * CC * CC];                      // W_attn^T [3072,K]
__device__ __half g_wp[CC * CC];                          // W_proj^T [1024,K]
__device__ __half g_q[BB * HH * TT * DD];                 // [B,H,T,D] scaled fp16
__device__ __half g_k[BB * HH * TT * DD];                 // [B,H,T,D]
__device__ __half g_v[BB * HH * TT * DD];                 // [B,H,T,D] (natural)
__device__ __half g_at[MROWS * CC];                       // att fp16 [M,K]
__device__ uint32_t g_ctr[2];                             // work-steal counters

// ---------------------------------------------------------------------------
// PTX helpers
// ---------------------------------------------------------------------------
__device__ __forceinline__ void mma_f16(float* c, const uint32_t* a,
                                        const uint32_t* b) {
    asm volatile(
        "mma.sync.aligned.m16n8k16.row.col.f32.f16.f16.f32 "
        "{%0,%1,%2,%3}, {%4,%5,%6,%7}, {%8,%9}, {%0,%1,%2,%3};"
        : "+f"(c[0]), "+f"(c[1]), "+f"(c[2]), "+f"(c[3])
        : "r"(a[0]), "r"(a[1]), "r"(a[2]), "r"(a[3]), "r"(b[0]), "r"(b[1]));
}
__device__ __forceinline__ void ldsm4(uint32_t* r, uint32_t addr) {
    asm volatile("ldmatrix.sync.aligned.m8n8.x4.shared.b16 {%0,%1,%2,%3}, [%4];"
                 : "=r"(r[0]), "=r"(r[1]), "=r"(r[2]), "=r"(r[3]) : "r"(addr));
}
__device__ __forceinline__ void ldsm4t(uint32_t* r, uint32_t addr) {
    asm volatile("ldmatrix.sync.aligned.m8n8.x4.trans.shared.b16 {%0,%1,%2,%3}, [%4];"
                 : "=r"(r[0]), "=r"(r[1]), "=r"(r[2]), "=r"(r[3]) : "r"(addr));
}
__device__ __forceinline__ float ex2f(float x) {
    float y;
    asm("ex2.approx.f32 %0, %1;" : "=f"(y) : "f"(x));
    return y;
}
__device__ __forceinline__ uint32_t pack_f16(float lo, float hi) {
    __half2 h = __float22half2_rn(make_float2(lo, hi));
    return *(uint32_t*)&h;
}
__device__ __forceinline__ void cp16(uint32_t s, const void* g) {
    asm volatile("cp.async.cg.shared.global [%0], [%1], 16;" :: "r"(s), "l"(g));
}
__device__ __forceinline__ void cp_commit() {
    asm volatile("cp.async.commit_group;" ::: "memory");
}
__device__ __forceinline__ void cp_wait1() {
    asm volatile("cp.async.wait_group 1;" ::: "memory");
}
__device__ __forceinline__ void cp_wait0() {
    asm volatile("cp.async.wait_group 0;" ::: "memory");
}

// ---------------------------------------------------------------------------
// Fused prep: x convert + both weight transposes + counter reset.
// ---------------------------------------------------------------------------
__device__ __forceinline__ void wt_block(const float* __restrict__ W,
                                         __half* __restrict__ Wt,
                                         int K, int N, int bx, int by, int tid) {
    __shared__ float t[32][33];
    const int tx = tid & 31, ty = tid >> 5;   // 32 x 8
    const int n0 = bx * 32, k0 = by * 32;
#pragma unroll
    for (int i = 0; i < 4; i++)
        t[ty + i * 8][tx] = W[(size_t)(k0 + ty + i * 8) * N + n0 + tx];
    __syncthreads();
#pragma unroll
    for (int i = 0; i < 4; i++)
        Wt[(size_t)(n0 + ty + i * 8) * K + k0 + tx] = __float2half(t[tx][ty + i * 8]);
}

__global__ void prep_all(const float* __restrict__ x, __half* __restrict__ xp,
                         const float* __restrict__ Wa, __half* __restrict__ wa,
                         const float* __restrict__ Wp, __half* __restrict__ wp)
{
    const int b = blockIdx.x;
    const int tid = threadIdx.x;
    if (b == 0 && tid < 2) g_ctr[tid] = 0;   // reset work-steal counters
    if (b < 8192) {
        int idx = b * 256 + tid;
        float4 v = ((const float4*)x)[idx];
        *(uint32_t*)(xp + (size_t)idx * 4)     = pack_f16(v.x, v.y);
        *(uint32_t*)(xp + (size_t)idx * 4 + 2) = pack_f16(v.z, v.w);
    } else if (b < 8192 + 3072) {
        int bb = b - 8192;
        wt_block(Wa, wa, CC, 3 * CC, bb % 96, bb / 96, tid);
    } else {
        int bb = b - 11264;
        wt_block(Wp, wp, CC, CC, bb % 32, bb / 32, tid);
    }
}

// ---------------------------------------------------------------------------
// Persistent fp16 GEMM with atomic work-stealing over 128x128 tiles.
// 4 warps (2x2), warp tile 64x64, K-chunk 32, 3-stage cp.async.
// MODE 0: fp32 row-major out. MODE 1: QKV epilogue (fp16 q/k/v outputs).
// ---------------------------------------------------------------------------
#define ROWB 80
#define TILE_B (128 * ROWB)           // 10240
#define NSTG 3
#define STAGE_B (2 * TILE_B)          // 20480 (A, B)
#define GEMM_SMEM (NSTG * STAGE_B)    // 61440

template <int MODE>
__global__ void __launch_bounds__(128, 2) mma_gemm(
    const __half* __restrict__ A_, const __half* __restrict__ B_,
    const float* __restrict__ bias,
    float* __restrict__ Cout,
    __half* __restrict__ Q_o, __half* __restrict__ K_o, __half* __restrict__ V_o,
    int N, int K, int ntiles, int nx, uint32_t* __restrict__ ctr)
{
    extern __shared__ char smg[];
    __shared__ int s_tile;
    const uint32_t sbase = (uint32_t)__cvta_generic_to_shared(smg);
    const int tid = threadIdx.x;
    const int wid = tid >> 5, lane = tid & 31;
    const int wm = wid >> 1, wn = wid & 1;
    const int g = lane >> 2, tg = lane & 3;
    const int lrow = lane & 15, lhalf = lane >> 4;

    const uint32_t aoff = (uint32_t)((wm * 64 + lrow) * ROWB + lhalf * 16);
    const uint32_t boff = (uint32_t)((wn * 64 + lrow) * ROWB + lhalf * 16) + TILE_B;
    const int NCH = K / 32;

    for (;;) {
        if (tid == 0) s_tile = (int)atomicAdd(ctr, 1u);
        __syncthreads();   // also guarantees prior tile fully done before reuse
        const int tile = s_tile;
        if (tile >= ntiles) return;

        const int m0 = (tile / nx) * 128, n0 = (tile % nx) * 128;
        const __half* A = A_ + (size_t)m0 * K;
        const __half* B = B_ + (size_t)n0 * K;
        const __half* tp[2] = { A, B };

        float acc[4][8][4];
#pragma unroll
        for (int mt = 0; mt < 4; mt++)
#pragma unroll
            for (int nt = 0; nt < 8; nt++)
#pragma unroll
                for (int i = 0; i < 4; i++) acc[mt][nt][i] = 0.0f;

#define GEMM_ISSUE(chunk) do {                                                 \
    const uint32_t _sb = sbase + ((chunk) % NSTG) * STAGE_B;                   \
    const int _kc = (chunk) * 32;                                              \
    _Pragma("unroll")                                                          \
    for (int _i = 0; _i < 8; _i++) {                                           \
        int _e = _i * 128 + tid;                                               \
        int _t = _e >> 9, _r = (_e & 511) >> 2, _h = _e & 3;                   \
        cp16(_sb + _t * TILE_B + _r * ROWB + _h * 16,                          \
             tp[_t] + (size_t)_r * K + _kc + _h * 8);                          \
    }                                                                          \
} while (0)

        GEMM_ISSUE(0); cp_commit();
        GEMM_ISSUE(1); cp_commit();

        for (int c = 0; c < NCH; c++) {
            cp_wait1();
            __syncthreads();

            const uint32_t st = sbase + (c % NSTG) * STAGE_B;

#pragma unroll
            for (int ks = 0; ks < 2; ks++) {
                uint32_t ah[4][4];
#pragma unroll
                for (int mt = 0; mt < 4; mt++)
                    ldsm4(ah[mt], st + aoff + mt * 16 * ROWB + ks * 32);
#pragma unroll
                for (int p = 0; p < 4; p++) {
                    uint32_t rb[4];
                    ldsm4(rb, st + boff + p * 16 * ROWB + ks * 32);
                    uint32_t bE[2] = { rb[0], rb[2] }, bO[2] = { rb[1], rb[3] };
#pragma unroll
                    for (int mt = 0; mt < 4; mt++) mma_f16(acc[mt][2 * p],     ah[mt], bE);
#pragma unroll
                    for (int mt = 0; mt < 4; mt++) mma_f16(acc[mt][2 * p + 1], ah[mt], bO);
                }
            }

            if (c + 2 < NCH) GEMM_ISSUE(c + 2);
            cp_commit();   // empty group at tail keeps wait accounting uniform
        }
#undef GEMM_ISSUE

        // Epilogue
#pragma unroll
        for (int mt = 0; mt < 4; mt++) {
#pragma unroll
            for (int nt = 0; nt < 8; nt++) {
                const int cg = n0 + wn * 64 + nt * 8 + tg * 2;
                const int r0g = m0 + wm * 64 + mt * 16 + g;
                const float b0 = __ldg(bias + cg);
                const float b1 = __ldg(bias + cg + 1);
                float f00 = acc[mt][nt][0] + b0, f01 = acc[mt][nt][1] + b1;
                float f10 = acc[mt][nt][2] + b0, f11 = acc[mt][nt][3] + b1;
                if (MODE == 0) {
                    *(float2*)(Cout + (size_t)r0g * N + cg) = make_float2(f00, f01);
                    *(float2*)(Cout + (size_t)(r0g + 8) * N + cg) = make_float2(f10, f11);
                } else {
                    const int which = cg >> 10;
                    const int c10 = cg & 1023;
                    const int h = c10 >> 6;
                    const int d = c10 & 63;
                    const int br = r0g >> 11, tr = r0g & 2047;
                    const size_t i0 = ((((size_t)br * HH + h) * TT) + tr) * DD + d;
                    if (which == 0) {
                        *(uint32_t*)(Q_o + i0)          = pack_f16(f00 * QSC, f01 * QSC);
                        *(uint32_t*)(Q_o + i0 + 8 * DD) = pack_f16(f10 * QSC, f11 * QSC);
                    } else {
                        __half* base = (which == 1) ? K_o : V_o;
                        *(uint32_t*)(base + i0)          = pack_f16(f00, f01);
                        *(uint32_t*)(base + i0 + 8 * DD) = pack_f16(f10, f11);
                    }
                }
            }
        }
    }
}

// ---------------------------------------------------------------------------
// Flash attention (R12 config): fp16 mma (fp32 accum), 64-query tiles,
// 4 warps, V natural layout via ldmatrix.trans, 2-stage cp.async, 3 CTAs/SM.
// ---------------------------------------------------------------------------
#define ROWF 144
#define TILEF (64 * ROWF)   // 9216
#define FL_QH 0
#define FL_ST(s) (TILEF + (s) * 2 * TILEF)
#define FL_SMEM (5 * TILEF)  // 46080

__global__ void __launch_bounds__(128, 3) flash_mma(
    const __half* __restrict__ Qg,
    const __half* __restrict__ Kg, const __half* __restrict__ Vg,
    __half* __restrict__ at_o)
{
    extern __shared__ char smf[];
    const uint32_t sbase = (uint32_t)__cvta_generic_to_shared(smf);
    const int tid = threadIdx.x, wid = tid >> 5, lane = tid & 31;
    const int g = lane >> 2, tg = lane & 3;
    const int qt = 31 - blockIdx.x;
    const int bh = blockIdx.y;

    const __half* Qb = Qg + (size_t)bh * TT * DD;
    const __half* Kb = Kg + (size_t)bh * TT * DD;
    const __half* Vb = Vg + (size_t)bh * TT * DD;

    const int lrow = lane & 15, lhalf = lane >> 4;

#define ISSUE_KV(stg, kvi) do {                                                \
    const uint32_t _sb = sbase + FL_ST(stg);                                   \
    _Pragma("unroll")                                                          \
    for (int _i = 0; _i < 4; _i++) {                                           \
        int _ch = _i * 128 + tid;                                              \
        int _row = _ch >> 3, _c = _ch & 7;                                     \
        cp16(_sb + _row * ROWF + _c * 16,                                      \
             Kb + (size_t)(kvi) * 4096 + _ch * 8);                             \
        cp16(_sb + TILEF + _row * ROWF + _c * 16,                              \
             Vb + (size_t)(kvi) * 4096 + _ch * 8);                             \
    }                                                                          \
} while (0)

    // Prologue: Q tile (group 0), KV tile 0 (group 1)
#pragma unroll
    for (int i = 0; i < 4; i++) {
        int ch = i * 128 + tid;
        int row = ch >> 3, c = ch & 7;
        cp16(sbase + FL_QH + row * ROWF + c * 16, Qb + (size_t)qt * 4096 + ch * 8);
    }
    cp_commit();
    ISSUE_KV(0, 0);
    cp_commit();
    cp_wait1();
    __syncthreads();

    // Q fragments via ldmatrix (held for whole kernel)
    uint32_t qf[4][4];
    {
        const uint32_t qoff = sbase + (uint32_t)((wid * 16 + lrow) * ROWF + lhalf * 16);
#pragma unroll
        for (int j = 0; j < 4; j++) ldsm4(qf[j], qoff + FL_QH + j * 32);
    }

    float oacc[8][4];
#pragma unroll
    for (int i = 0; i < 8; i++)
#pragma unroll
        for (int jj = 0; jj < 4; jj++) oacc[i][jj] = 0.0f;
    float m0 = -1e30f, m1 = -1e30f, l0 = 0.0f, l1 = 0.0f;

    const uint32_t foff = (uint32_t)(lrow * ROWF + lhalf * 16);
    const uint32_t voff = (uint32_t)(((lane >> 4) * 8 + (lane & 7)) * ROWF
                                     + ((lane >> 3) & 1) * 16);

    for (int kv = 0; kv <= qt; kv++) {
        const int s = kv & 1;
        if (kv < qt) { ISSUE_KV(s ^ 1, kv + 1); cp_commit(); cp_wait1(); }
        else cp_wait0();
        __syncthreads();

        const uint32_t KHs = sbase + FL_ST(s) + foff;
        const uint32_t VHs = sbase + FL_ST(s) + TILEF + voff;

        // S = Q @ K^T  (fp32 accumulators)
        float sa[8][4];
#pragma unroll
        for (int nt = 0; nt < 8; nt++)
#pragma unroll
            for (int jj = 0; jj < 4; jj++) sa[nt][jj] = 0.0f;

#pragma unroll
        for (int j = 0; j < 4; j++) {
            uint32_t rk[4][4];
#pragma unroll
            for (int p = 0; p < 4; p++) ldsm4(rk[p], KHs + p * 16 * ROWF + j * 32);
#pragma unroll
            for (int p = 0; p < 4; p++) {
                uint32_t bE[2] = { rk[p][0], rk[p][2] }, bO[2] = { rk[p][1], rk[p][3] };
                mma_f16(sa[2 * p],     qf[j], bE);
                mma_f16(sa[2 * p + 1], qf[j], bO);
            }
        }

        // Causal mask (diagonal tile only)
        if (kv == qt) {
            const int r0 = wid * 16 + g, r1 = r0 + 8;
#pragma unroll
            for (int nt = 0; nt < 8; nt++) {
                int c0 = nt * 8 + tg * 2;
                if (c0 > r0)     sa[nt][0] = -1e30f;
                if (c0 + 1 > r0) sa[nt][1] = -1e30f;
                if (c0 > r1)     sa[nt][2] = -1e30f;
                if (c0 + 1 > r1) sa[nt][3] = -1e30f;
            }
        }

        // Online softmax (log2 domain)
        float mt0 = sa[0][0], mt1 = sa[0][2];
#pragma unroll
        for (int nt = 0; nt < 8; nt++) {
            mt0 = fmaxf(mt0, fmaxf(sa[nt][0], sa[nt][1]));
            mt1 = fmaxf(mt1, fmaxf(sa[nt][2], sa[nt][3]));
        }
        mt0 = fmaxf(mt0, __shfl_xor_sync(0xffffffffu, mt0, 1));
        mt0 = fmaxf(mt0, __shfl_xor_sync(0xffffffffu, mt0, 2));
        mt1 = fmaxf(mt1, __shfl_xor_sync(0xffffffffu, mt1, 1));
        mt1 = fmaxf(mt1, __shfl_xor_sync(0xffffffffu, mt1, 2));

        float mn0 = fmaxf(m0, mt0), mn1 = fmaxf(m1, mt1);
        float cr0 = ex2f(m0 - mn0), cr1 = ex2f(m1 - mn1);
        m0 = mn0; m1 = mn1;

        float s0 = 0.0f, s1 = 0.0f;
#pragma unroll
        for (int nt = 0; nt < 8; nt++) {
            sa[nt][0] = ex2f(sa[nt][0] - mn0);
            sa[nt][1] = ex2f(sa[nt][1] - mn0);
            sa[nt][2] = ex2f(sa[nt][2] - mn1);
            sa[nt][3] = ex2f(sa[nt][3] - mn1);
            s0 += sa[nt][0] + sa[nt][1];
            s1 += sa[nt][2] + sa[nt][3];
        }
        s0 += __shfl_xor_sync(0xffffffffu, s0, 1);
        s0 += __shfl_xor_sync(0xffffffffu, s0, 2);
        s1 += __shfl_xor_sync(0xffffffffu, s1, 1);
        s1 += __shfl_xor_sync(0xffffffffu, s1, 2);
        l0 = l0 * cr0 + s0;
        l1 = l1 * cr1 + s1;

#pragma unroll
        for (int nt = 0; nt < 8; nt++) {
            oacc[nt][0] *= cr0; oacc[nt][1] *= cr0;
            oacc[nt][2] *= cr1; oacc[nt][3] *= cr1;
        }

        // Pack P to fp16 A-fragments
        uint32_t pa[4][4];
#pragma unroll
        for (int j = 0; j < 4; j++) {
            pa[j][0] = pack_f16(sa[2 * j][0], sa[2 * j][1]);
            pa[j][1] = pack_f16(sa[2 * j][2], sa[2 * j][3]);
            pa[j][2] = pack_f16(sa[2 * j + 1][0], sa[2 * j + 1][1]);
            pa[j][3] = pack_f16(sa[2 * j + 1][2], sa[2 * j + 1][3]);
        }

        // O += P @ V  (V natural layout, trans ldmatrix; fp32 acc)
#pragma unroll
        for (int j = 0; j < 4; j++) {
            uint32_t rv[4][4];
#pragma unroll
            for (int p = 0; p < 4; p++)
                ldsm4t(rv[p], VHs + j * 16 * ROWF + p * 32);
#pragma unroll
            for (int p = 0; p < 4; p++) {
                uint32_t bE[2] = { rv[p][0], rv[p][2] }, bO[2] = { rv[p][1], rv[p][3] };
                mma_f16(oacc[2 * p],     pa[j], bE);
                mma_f16(oacc[2 * p + 1], pa[j], bO);
            }
        }
        __syncthreads();
    }

    // Epilogue: normalize, write att fp16 [M=B*T, C] (c = h*64+d)
    const float i0 = 1.0f / l0, i1 = 1.0f / l1;
    const int b = bh >> 4, h = bh & 15;
    const int t0 = qt * 64 + wid * 16 + g;
    const size_t row0 = ((size_t)b * TT + t0) * CC + h * DD;
    const size_t row1 = row0 + (size_t)8 * CC;
#pragma unroll
    for (int nt = 0; nt < 8; nt++) {
        const int d = nt * 8 + tg * 2;
        *(uint32_t*)(at_o + row0 + d) = pack_f16(oacc[nt][0] * i0, oacc[nt][1] * i0);
        *(uint32_t*)(at_o + row1 + d) = pack_f16(oacc[nt][2] * i1, oacc[nt][3] * i1);
    }
#undef ISSUE_KV
}

// ---------------------------------------------------------------------------
extern "C" void kernel_launch(void* const* d_in, const int* in_sizes, int n_in,
                              void* d_out, int out_size)
{
    (void)in_sizes; (void)n_in; (void)out_size;
    const float* x      = (const float*)d_in[0];
    const float* W_attn = (const float*)d_in[1];
    const float* b_attn = (const float*)d_in[2];
    const float* W_proj = (const float*)d_in[3];
    const float* b_proj = (const float*)d_in[4];
    float* out = (float*)d_out;

    __half *xp, *wa, *wp, *at, *q, *k, *v;
    uint32_t* ctr;
    cudaGetSymbolAddress((void**)&xp, g_x);
    cudaGetSymbolAddress((void**)&wa, g_wa);
    cudaGetSymbolAddress((void**)&wp, g_wp);
    cudaGetSymbolAddress((void**)&at, g_at);
    cudaGetSymbolAddress((void**)&q, g_q);
    cudaGetSymbolAddress((void**)&k, g_k);
    cudaGetSymbolAddress((void**)&v, g_v);
    cudaGetSymbolAddress((void**)&ctr, g_ctr);

    cudaFuncSetAttribute((const void*)mma_gemm<1>,
                         cudaFuncAttributeMaxDynamicSharedMemorySize, GEMM_SMEM);
    cudaFuncSetAttribute((const void*)mma_gemm<0>,
                         cudaFuncAttributeMaxDynamicSharedMemorySize, GEMM_SMEM);
    cudaFuncSetAttribute((const void*)flash_mma,
                         cudaFuncAttributeMaxDynamicSharedMemorySize, FL_SMEM);

    // 1) Fused prep: x convert + weight transposes + counter reset
    prep_all<<<12288, 256>>>(x, xp, W_attn, wa, W_proj, wp);

    // 2) QKV GEMM (persistent, work-stealing): 1536 tiles of 128x128
    mma_gemm<1><<<304, 128, GEMM_SMEM>>>(
        xp, wa, b_attn, nullptr, q, k, v, 3 * CC, CC, 1536, 24, ctr);

    // 3) Flash attention (64-query tiles) -> att fp16
    flash_mma<<<dim3(TT / 64, BB * HH), 128, FL_SMEM>>>(q, k, v, at);

    // 4) Projection GEMM (persistent, work-stealing): 512 tiles
    mma_gemm<0><<<304, 128, GEMM_SMEM>>>(
        at, wp, b_proj, out, nullptr, nullptr, nullptr, CC, CC, 512, 8, ctr + 1);
}

// round 16
// speedup vs baseline: 1.0072x; 1.0072x over previous
#include <cuda_runtime.h>
#include <cuda_bf16.h>
#include <cuda_fp16.h>
#include <math.h>
#include <stdint.h>

// Problem constants
#define BB 4
#define TT 2048
#define CC 1024
#define HH 16
#define DD 64
#define MROWS (BB * TT)   // 8192
#define QSC (0.125f * 1.44269504088896f)   // 1/sqrt(D) * log2(e), folded into Q

// ---------------------------------------------------------------------------
// Scratch (device globals)
// ---------------------------------------------------------------------------
__device__ __half g_x[MROWS * CC];                        // x fp16 [M,K]
__device__ __half g_wa[3 * CC * CC];                      // W_attn^T [3072,K]
__device__ __half g_wp[CC * CC];                          // W_proj^T [1024,K]
__device__ __half g_q[BB * HH * TT * DD];                 // [B,H,T,D] scaled fp16
__device__ __half g_k[BB * HH * TT * DD];                 // [B,H,T,D]
__device__ __half g_v[BB * HH * TT * DD];                 // [B,H,T,D] (natural)
__device__ __half g_at[MROWS * CC];                       // att fp16 [M,K]

// ---------------------------------------------------------------------------
// PTX helpers
// ---------------------------------------------------------------------------
__device__ __forceinline__ void mma_f16(float* c, const uint32_t* a,
                                        const uint32_t* b) {
    asm volatile(
        "mma.sync.aligned.m16n8k16.row.col.f32.f16.f16.f32 "
        "{%0,%1,%2,%3}, {%4,%5,%6,%7}, {%8,%9}, {%0,%1,%2,%3};"
        : "+f"(c[0]), "+f"(c[1]), "+f"(c[2]), "+f"(c[3])
        : "r"(a[0]), "r"(a[1]), "r"(a[2]), "r"(a[3]), "r"(b[0]), "r"(b[1]));
}
__device__ __forceinline__ void ldsm4(uint32_t* r, uint32_t addr) {
    asm volatile("ldmatrix.sync.aligned.m8n8.x4.shared.b16 {%0,%1,%2,%3}, [%4];"
                 : "=r"(r[0]), "=r"(r[1]), "=r"(r[2]), "=r"(r[3]) : "r"(addr));
}
__device__ __forceinline__ void ldsm4t(uint32_t* r, uint32_t addr) {
    asm volatile("ldmatrix.sync.aligned.m8n8.x4.trans.shared.b16 {%0,%1,%2,%3}, [%4];"
                 : "=r"(r[0]), "=r"(r[1]), "=r"(r[2]), "=r"(r[3]) : "r"(addr));
}
__device__ __forceinline__ float ex2f(float x) {
    float y;
    asm("ex2.approx.f32 %0, %1;" : "=f"(y) : "f"(x));
    return y;
}
__device__ __forceinline__ uint32_t pack_f16(float lo, float hi) {
    __half2 h = __float22half2_rn(make_float2(lo, hi));
    return *(uint32_t*)&h;
}
__device__ __forceinline__ void cp16(uint32_t s, const void* g) {
    asm volatile("cp.async.cg.shared.global [%0], [%1], 16;" :: "r"(s), "l"(g));
}
__device__ __forceinline__ void cp_commit() {
    asm volatile("cp.async.commit_group;" ::: "memory");
}
__device__ __forceinline__ void cp_wait1() {
    asm volatile("cp.async.wait_group 1;" ::: "memory");
}
__device__ __forceinline__ void cp_wait0() {
    asm volatile("cp.async.wait_group 0;" ::: "memory");
}

// ---------------------------------------------------------------------------
// Fused prep: one launch does x fp32->fp16 convert + both weight transposes.
// ---------------------------------------------------------------------------
__device__ __forceinline__ void wt_block(const float* __restrict__ W,
                                         __half* __restrict__ Wt,
                                         int K, int N, int bx, int by, int tid) {
    __shared__ float t[32][33];
    const int tx = tid & 31, ty = tid >> 5;   // 32 x 8
    const int n0 = bx * 32, k0 = by * 32;
#pragma unroll
    for (int i = 0; i < 4; i++)
        t[ty + i * 8][tx] = W[(size_t)(k0 + ty + i * 8) * N + n0 + tx];
    __syncthreads();
#pragma unroll
    for (int i = 0; i < 4; i++)
        Wt[(size_t)(n0 + ty + i * 8) * K + k0 + tx] = __float2half(t[tx][ty + i * 8]);
}

__global__ void prep_all(const float* __restrict__ x, __half* __restrict__ xp,
                         const float* __restrict__ Wa, __half* __restrict__ wa,
                         const float* __restrict__ Wp, __half* __restrict__ wp)
{
    const int b = blockIdx.x;
    const int tid = threadIdx.x;
    if (b < 8192) {
        int idx = b * 256 + tid;
        float4 v = ((const float4*)x)[idx];
        *(uint32_t*)(xp + (size_t)idx * 4)     = pack_f16(v.x, v.y);
        *(uint32_t*)(xp + (size_t)idx * 4 + 2) = pack_f16(v.z, v.w);
    } else if (b < 8192 + 3072) {
        int bb = b - 8192;
        wt_block(Wa, wa, CC, 3 * CC, bb % 96, bb / 96, tid);
    } else {
        int bb = b - 11264;
        wt_block(Wp, wp, CC, CC, bb % 32, bb / 32, tid);
    }
}

// ---------------------------------------------------------------------------
// fp16 GEMM: C = A @ B^T + bias (single fp16 A and B).
// CTA 128x128, 4 warps (2x2), warp tile 64x64, K-chunk 32, 3-stage cp.async.
// MODE 0: fp32 row-major out. MODE 1: QKV epilogue (fp16 q/k/v outputs).
// ---------------------------------------------------------------------------
#define ROWB 80
#define TILE_B (128 * ROWB)           // 10240
#define NSTG 3
#define STAGE_B (2 * TILE_B)          // 20480 (A, B)
#define GEMM_SMEM (NSTG * STAGE_B)    // 61440

template <int MODE>
__global__ void __launch_bounds__(128, 2) mma_gemm(
    const __half* __restrict__ A_, const __half* __restrict__ B_,
    const float* __restrict__ bias,
    float* __restrict__ Cout,
    __half* __restrict__ Q_o, __half* __restrict__ K_o, __half* __restrict__ V_o,
    int N, int K)
{
    extern __shared__ char smg[];
    const uint32_t sbase = (uint32_t)__cvta_generic_to_shared(smg);
    const int tid = threadIdx.x;
    const int wid = tid >> 5, lane = tid & 31;
    const int wm = wid >> 1, wn = wid & 1;
    const int g = lane >> 2, tg = lane & 3;
    const int lrow = lane & 15, lhalf = lane >> 4;
    const int m0 = blockIdx.y * 128, n0 = blockIdx.x * 128;

    const __half* A = A_ + (size_t)m0 * K;
    const __half* B = B_ + (size_t)n0 * K;
    const __half* tp[2] = { A, B };

    const uint32_t aoff = (uint32_t)((wm * 64 + lrow) * ROWB + lhalf * 16);
    const uint32_t boff = (uint32_t)((wn * 64 + lrow) * ROWB + lhalf * 16) + TILE_B;

    float acc[4][8][4];
#pragma unroll
    for (int mt = 0; mt < 4; mt++)
#pragma unroll
        for (int nt = 0; nt < 8; nt++)
#pragma unroll
            for (int i = 0; i < 4; i++) acc[mt][nt][i] = 0.0f;

#define GEMM_ISSUE(chunk) do {                                                 \
    const uint32_t _sb = sbase + ((chunk) % NSTG) * STAGE_B;                   \
    const int _kc = (chunk) * 32;                                              \
    _Pragma("unroll")                                                          \
    for (int _i = 0; _i < 8; _i++) {                                           \
        int _e = _i * 128 + tid;                                               \
        int _t = _e >> 9, _r = (_e & 511) >> 2, _h = _e & 3;                   \
        cp16(_sb + _t * TILE_B + _r * ROWB + _h * 16,                          \
             tp[_t] + (size_t)_r * K + _kc + _h * 8);                          \
    }                                                                          \
} while (0)

    const int NCH = K / 32;
    GEMM_ISSUE(0); cp_commit();
    GEMM_ISSUE(1); cp_commit();

    for (int c = 0; c < NCH; c++) {
        cp_wait1();
        __syncthreads();

        const uint32_t st = sbase + (c % NSTG) * STAGE_B;

#pragma unroll
        for (int ks = 0; ks < 2; ks++) {
            uint32_t ah[4][4];
#pragma unroll
            for (int mt = 0; mt < 4; mt++)
                ldsm4(ah[mt], st + aoff + mt * 16 * ROWB + ks * 32);
#pragma unroll
            for (int p = 0; p < 4; p++) {
                uint32_t rb[4];
                ldsm4(rb, st + boff + p * 16 * ROWB + ks * 32);
                uint32_t bE[2] = { rb[0], rb[2] }, bO[2] = { rb[1], rb[3] };
#pragma unroll
                for (int mt = 0; mt < 4; mt++) mma_f16(acc[mt][2 * p],     ah[mt], bE);
#pragma unroll
                for (int mt = 0; mt < 4; mt++) mma_f16(acc[mt][2 * p + 1], ah[mt], bO);
            }
        }

        if (c + 2 < NCH) GEMM_ISSUE(c + 2);
        cp_commit();   // empty group at tail keeps wait accounting uniform
    }
#undef GEMM_ISSUE

    // Epilogue
#pragma unroll
    for (int mt = 0; mt < 4; mt++) {
#pragma unroll
        for (int nt = 0; nt < 8; nt++) {
            const int cg = n0 + wn * 64 + nt * 8 + tg * 2;
            const int r0g = m0 + wm * 64 + mt * 16 + g;
            const float b0 = __ldg(bias + cg);
            const float b1 = __ldg(bias + cg + 1);
            float f00 = acc[mt][nt][0] + b0, f01 = acc[mt][nt][1] + b1;
            float f10 = acc[mt][nt][2] + b0, f11 = acc[mt][nt][3] + b1;
            if (MODE == 0) {
                *(float2*)(Cout + (size_t)r0g * N + cg) = make_float2(f00, f01);
                *(float2*)(Cout + (size_t)(r0g + 8) * N + cg) = make_float2(f10, f11);
            } else {
                const int which = cg >> 10;
                const int c10 = cg & 1023;
                const int h = c10 >> 6;
                const int d = c10 & 63;
                const int br = r0g >> 11, tr = r0g & 2047;
                const size_t i0 = ((((size_t)br * HH + h) * TT) + tr) * DD + d;
                if (which == 0) {
                    *(uint32_t*)(Q_o + i0)          = pack_f16(f00 * QSC, f01 * QSC);
                    *(uint32_t*)(Q_o + i0 + 8 * DD) = pack_f16(f10 * QSC, f11 * QSC);
                } else {
                    __half* base = (which == 1) ? K_o : V_o;
                    *(uint32_t*)(base + i0)          = pack_f16(f00, f01);
                    *(uint32_t*)(base + i0 + 8 * DD) = pack_f16(f10, f11);
                }
            }
        }
    }
}

// ---------------------------------------------------------------------------
// Flash attention: fp16 mma (fp32 accum), 64-query tiles, 4 warps,
// V natural layout via ldmatrix.trans, 2-stage cp.async, 4 CTAs/SM.
// ---------------------------------------------------------------------------
#define ROWF 144
#define TILEF (64 * ROWF)   // 9216
#define FL_QH 0
#define FL_ST(s) (TILEF + (s) * 2 * TILEF)
#define FL_SMEM (5 * TILEF)  // 46080

__global__ void __launch_bounds__(128, 4) flash_mma(
    const __half* __restrict__ Qg,
    const __half* __restrict__ Kg, const __half* __restrict__ Vg,
    __half* __restrict__ at_o)
{
    extern __shared__ char smf[];
    const uint32_t sbase = (uint32_t)__cvta_generic_to_shared(smf);
    const int tid = threadIdx.x, wid = tid >> 5, lane = tid & 31;
    const int g = lane >> 2, tg = lane & 3;
    const int qt = 31 - blockIdx.x;
    const int bh = blockIdx.y;

    const __half* Qb = Qg + (size_t)bh * TT * DD;
    const __half* Kb = Kg + (size_t)bh * TT * DD;
    const __half* Vb = Vg + (size_t)bh * TT * DD;

    const int lrow = lane & 15, lhalf = lane >> 4;

#define ISSUE_KV(stg, kvi) do {                                                \
    const uint32_t _sb = sbase + FL_ST(stg);                                   \
    _Pragma("unroll")                                                          \
    for (int _i = 0; _i < 4; _i++) {                                           \
        int _ch = _i * 128 + tid;                                              \
        int _row = _ch >> 3, _c = _ch & 7;                                     \
        cp16(_sb + _row * ROWF + _c * 16,                                      \
             Kb + (size_t)(kvi) * 4096 + _ch * 8);                             \
        cp16(_sb + TILEF + _row * ROWF + _c * 16,                              \
             Vb + (size_t)(kvi) * 4096 + _ch * 8);                             \
    }                                                                          \
} while (0)

    // Prologue: Q tile (group 0), KV tile 0 (group 1)
#pragma unroll
    for (int i = 0; i < 4; i++) {
        int ch = i * 128 + tid;
        int row = ch >> 3, c = ch & 7;
        cp16(sbase + FL_QH + row * ROWF + c * 16, Qb + (size_t)qt * 4096 + ch * 8);
    }
    cp_commit();
    ISSUE_KV(0, 0);
    cp_commit();
    cp_wait1();
    __syncthreads();

    // Q fragments via ldmatrix (held for whole kernel)
    uint32_t qf[4][4];
    {
        const uint32_t qoff = sbase + (uint32_t)((wid * 16 + lrow) * ROWF + lhalf * 16);
#pragma unroll
        for (int j = 0; j < 4; j++) ldsm4(qf[j], qoff + FL_QH + j * 32);
    }

    float oacc[8][4];
#pragma unroll
    for (int i = 0; i < 8; i++)
#pragma unroll
        for (int jj = 0; jj < 4; jj++) oacc[i][jj] = 0.0f;
    float m0 = -1e30f, m1 = -1e30f, l0 = 0.0f, l1 = 0.0f;

    const uint32_t foff = (uint32_t)(lrow * ROWF + lhalf * 16);
    const uint32_t voff = (uint32_t)(((lane >> 4) * 8 + (lane & 7)) * ROWF
                                     + ((lane >> 3) & 1) * 16);

    for (int kv = 0; kv <= qt; kv++) {
        const int s = kv & 1;
        if (kv < qt) { ISSUE_KV(s ^ 1, kv + 1); cp_commit(); cp_wait1(); }
        else cp_wait0();
        __syncthreads();

        const uint32_t KHs = sbase + FL_ST(s) + foff;
        const uint32_t VHs = sbase + FL_ST(s) + TILEF + voff;

        // S = Q @ K^T  (fp32 accumulators)
        float sa[8][4];
#pragma unroll
        for (int nt = 0; nt < 8; nt++)
#pragma unroll
            for (int jj = 0; jj < 4; jj++) sa[nt][jj] = 0.0f;

#pragma unroll
        for (int j = 0; j < 4; j++) {
            uint32_t rk[4][4];
#pragma unroll
            for (int p = 0; p < 4; p++) ldsm4(rk[p], KHs + p * 16 * ROWF + j * 32);
#pragma unroll
            for (int p = 0; p < 4; p++) {
                uint32_t bE[2] = { rk[p][0], rk[p][2] }, bO[2] = { rk[p][1], rk[p][3] };
                mma_f16(sa[2 * p],     qf[j], bE);
                mma_f16(sa[2 * p + 1], qf[j], bO);
            }
        }

        // Causal mask (diagonal tile only)
        if (kv == qt) {
            const int r0 = wid * 16 + g, r1 = r0 + 8;
#pragma unroll
            for (int nt = 0; nt < 8; nt++) {
                int c0 = nt * 8 + tg * 2;
                if (c0 > r0)     sa[nt][0] = -1e30f;
                if (c0 + 1 > r0) sa[nt][1] = -1e30f;
                if (c0 > r1)     sa[nt][2] = -1e30f;
                if (c0 + 1 > r1) sa[nt][3] = -1e30f;
            }
        }

        // Online softmax (log2 domain)
        float mt0 = sa[0][0], mt1 = sa[0][2];
#pragma unroll
        for (int nt = 0; nt < 8; nt++) {
            mt0 = fmaxf(mt0, fmaxf(sa[nt][0], sa[nt][1]));
            mt1 = fmaxf(mt1, fmaxf(sa[nt][2], sa[nt][3]));
        }
        mt0 = fmaxf(mt0, __shfl_xor_sync(0xffffffffu, mt0, 1));
        mt0 = fmaxf(mt0, __shfl_xor_sync(0xffffffffu, mt0, 2));
        mt1 = fmaxf(mt1, __shfl_xor_sync(0xffffffffu, mt1, 1));
        mt1 = fmaxf(mt1, __shfl_xor_sync(0xffffffffu, mt1, 2));

        float mn0 = fmaxf(m0, mt0), mn1 = fmaxf(m1, mt1);
        float cr0 = ex2f(m0 - mn0), cr1 = ex2f(m1 - mn1);
        m0 = mn0; m1 = mn1;

        float s0 = 0.0f, s1 = 0.0f;
#pragma unroll
        for (int nt = 0; nt < 8; nt++) {
            sa[nt][0] = ex2f(sa[nt][0] - mn0);
            sa[nt][1] = ex2f(sa[nt][1] - mn0);
            sa[nt][2] = ex2f(sa[nt][2] - mn1);
            sa[nt][3] = ex2f(sa[nt][3] - mn1);
            s0 += sa[nt][0] + sa[nt][1];
            s1 += sa[nt][2] + sa[nt][3];
        }
        s0 += __shfl_xor_sync(0xffffffffu, s0, 1);
        s0 += __shfl_xor_sync(0xffffffffu, s0, 2);
        s1 += __shfl_xor_sync(0xffffffffu, s1, 1);
        s1 += __shfl_xor_sync(0xffffffffu, s1, 2);
        l0 = l0 * cr0 + s0;
        l1 = l1 * cr1 + s1;

#pragma unroll
        for (int nt = 0; nt < 8; nt++) {
            oacc[nt][0] *= cr0; oacc[nt][1] *= cr0;
            oacc[nt][2] *= cr1; oacc[nt][3] *= cr1;
        }

        // Pack P to fp16 A-fragments
        uint32_t pa[4][4];
#pragma unroll
        for (int j = 0; j < 4; j++) {
            pa[j][0] = pack_f16(sa[2 * j][0], sa[2 * j][1]);
            pa[j][1] = pack_f16(sa[2 * j][2], sa[2 * j][3]);
            pa[j][2] = pack_f16(sa[2 * j + 1][0], sa[2 * j + 1][1]);
            pa[j][3] = pack_f16(sa[2 * j + 1][2], sa[2 * j + 1][3]);
        }

        // O += P @ V  (V natural layout, trans ldmatrix; fp32 acc)
#pragma unroll
        for (int j = 0; j < 4; j++) {
            uint32_t rv[4][4];
#pragma unroll
            for (int p = 0; p < 4; p++)
                ldsm4t(rv[p], VHs + j * 16 * ROWF + p * 32);
#pragma unroll
            for (int p = 0; p < 4; p++) {
                uint32_t bE[2] = { rv[p][0], rv[p][2] }, bO[2] = { rv[p][1], rv[p][3] };
                mma_f16(oacc[2 * p],     pa[j], bE);
                mma_f16(oacc[2 * p + 1], pa[j], bO);
            }
        }
        __syncthreads();
    }

    // Epilogue: normalize, write att fp16 [M=B*T, C] (c = h*64+d)
    const float i0 = 1.0f / l0, i1 = 1.0f / l1;
    const int b = bh >> 4, h = bh & 15;
    const int t0 = qt * 64 + wid * 16 + g;
    const size_t row0 = ((size_t)b * TT + t0) * CC + h * DD;
    const size_t row1 = row0 + (size_t)8 * CC;
#pragma unroll
    for (int nt = 0; nt < 8; nt++) {
        const int d = nt * 8 + tg * 2;
        *(uint32_t*)(at_o + row0 + d) = pack_f16(oacc[nt][0] * i0, oacc[nt][1] * i0);
        *(uint32_t*)(at_o + row1 + d) = pack_f16(oacc[nt][2] * i1, oacc[nt][3] * i1);
    }
#undef ISSUE_KV
}

// ---------------------------------------------------------------------------
extern "C" void kernel_launch(void* const* d_in, const int* in_sizes, int n_in,
                              void* d_out, int out_size)
{
    (void)in_sizes; (void)n_in; (void)out_size;
    const float* x      = (const float*)d_in[0];
    const float* W_attn = (const float*)d_in[1];
    const float* b_attn = (const float*)d_in[2];
    const float* W_proj = (const float*)d_in[3];
    const float* b_proj = (const float*)d_in[4];
    float* out = (float*)d_out;

    __half *xp, *wa, *wp, *at, *q, *k, *v;
    cudaGetSymbolAddress((void**)&xp, g_x);
    cudaGetSymbolAddress((void**)&wa, g_wa);
    cudaGetSymbolAddress((void**)&wp, g_wp);
    cudaGetSymbolAddress((void**)&at, g_at);
    cudaGetSymbolAddress((void**)&q, g_q);
    cudaGetSymbolAddress((void**)&k, g_k);
    cudaGetSymbolAddress((void**)&v, g_v);

    cudaFuncSetAttribute((const void*)mma_gemm<1>,
                         cudaFuncAttributeMaxDynamicSharedMemorySize, GEMM_SMEM);
    cudaFuncSetAttribute((const void*)mma_gemm<0>,
                         cudaFuncAttributeMaxDynamicSharedMemorySize, GEMM_SMEM);
    cudaFuncSetAttribute((const void*)flash_mma,
                         cudaFuncAttributeMaxDynamicSharedMemorySize, FL_SMEM);

    // 1) Fused prep: x convert + both weight transposes in one launch
    prep_all<<<12288, 256>>>(x, xp, W_attn, wa, W_proj, wp);

    // 2) QKV GEMM -> q (scaled), k, v — all single fp16, [B,H,T,D]
    mma_gemm<1><<<dim3(3 * CC / 128, MROWS / 128), 128, GEMM_SMEM>>>(
        xp, wa, b_attn, nullptr, q, k, v, 3 * CC, CC);

    // 3) Flash attention (64-query tiles, 4 CTAs/SM) -> att fp16
    flash_mma<<<dim3(TT / 64, BB * HH), 128, FL_SMEM>>>(q, k, v, at);

    // 4) Projection GEMM -> out (fp32)
    mma_gemm<0><<<dim3(CC / 128, MROWS / 128), 128, GEMM_SMEM>>>(
        at, wp, b_proj, out, nullptr, nullptr, nullptr, CC, CC);
}

// round 17
// speedup vs baseline: 1.0959x; 1.0881x over previous
#include <cuda_runtime.h>
#include <cuda_bf16.h>
#include <cuda_fp16.h>
#include <math.h>
#include <stdint.h>

// Problem constants
#define BB 4
#define TT 2048
#define CC 1024
#define HH 16
#define DD 64
#define MROWS (BB * TT)   // 8192
#define QSC (0.125f * 1.44269504088896f)   // 1/sqrt(D) * log2(e), folded into Q

// ---------------------------------------------------------------------------
// Scratch (device globals)
// ---------------------------------------------------------------------------
__device__ __half g_x[MROWS * CC];                        // x fp16 [M,K]
__device__ __half g_wa[3 * CC * CC];                      // W_attn^T [3072,K]
__device__ __half g_wp[CC * CC];                          // W_proj^T [1024,K]
__device__ __half g_q[BB * HH * TT * DD];                 // [B,H,T,D] scaled fp16
__device__ __half g_k[BB * HH * TT * DD];                 // [B,H,T,D]
__device__ __half g_v[BB * HH * TT * DD];                 // [B,H,T,D] (natural)
__device__ __half g_at[MROWS * CC];                       // att fp16 [M,K]

// ---------------------------------------------------------------------------
// PTX helpers
// ---------------------------------------------------------------------------
__device__ __forceinline__ void mma_f16(float* c, const uint32_t* a,
                                        const uint32_t* b) {
    asm volatile(
        "mma.sync.aligned.m16n8k16.row.col.f32.f16.f16.f32 "
        "{%0,%1,%2,%3}, {%4,%5,%6,%7}, {%8,%9}, {%0,%1,%2,%3};"
        : "+f"(c[0]), "+f"(c[1]), "+f"(c[2]), "+f"(c[3])
        : "r"(a[0]), "r"(a[1]), "r"(a[2]), "r"(a[3]), "r"(b[0]), "r"(b[1]));
}
__device__ __forceinline__ void ldsm4(uint32_t* r, uint32_t addr) {
    asm volatile("ldmatrix.sync.aligned.m8n8.x4.shared.b16 {%0,%1,%2,%3}, [%4];"
                 : "=r"(r[0]), "=r"(r[1]), "=r"(r[2]), "=r"(r[3]) : "r"(addr));
}
__device__ __forceinline__ void ldsm4t(uint32_t* r, uint32_t addr) {
    asm volatile("ldmatrix.sync.aligned.m8n8.x4.trans.shared.b16 {%0,%1,%2,%3}, [%4];"
                 : "=r"(r[0]), "=r"(r[1]), "=r"(r[2]), "=r"(r[3]) : "r"(addr));
}
__device__ __forceinline__ float ex2f(float x) {
    float y;
    asm("ex2.approx.f32 %0, %1;" : "=f"(y) : "f"(x));
    return y;
}
__device__ __forceinline__ uint32_t pack_f16(float lo, float hi) {
    __half2 h = __float22half2_rn(make_float2(lo, hi));
    return *(uint32_t*)&h;
}
__device__ __forceinline__ void cp16(uint32_t s, const void* g) {
    asm volatile("cp.async.cg.shared.global [%0], [%1], 16;" :: "r"(s), "l"(g));
}
__device__ __forceinline__ void cp_commit() {
    asm volatile("cp.async.commit_group;" ::: "memory");
}
__device__ __forceinline__ void cp_wait1() {
    asm volatile("cp.async.wait_group 1;" ::: "memory");
}
__device__ __forceinline__ void cp_wait0() {
    asm volatile("cp.async.wait_group 0;" ::: "memory");
}

// ---------------------------------------------------------------------------
// Fused prep: one launch does x fp32->fp16 convert + both weight transposes.
// ---------------------------------------------------------------------------
__device__ __forceinline__ void wt_block(const float* __restrict__ W,
                                         __half* __restrict__ Wt,
                                         int K, int N, int bx, int by, int tid) {
    __shared__ float t[32][33];
    const int tx = tid & 31, ty = tid >> 5;   // 32 x 8
    const int n0 = bx * 32, k0 = by * 32;
#pragma unroll
    for (int i = 0; i < 4; i++)
        t[ty + i * 8][tx] = W[(size_t)(k0 + ty + i * 8) * N + n0 + tx];
    __syncthreads();
#pragma unroll
    for (int i = 0; i < 4; i++)
        Wt[(size_t)(n0 + ty + i * 8) * K + k0 + tx] = __float2half(t[tx][ty + i * 8]);
}

__global__ void prep_all(const float* __restrict__ x, __half* __restrict__ xp,
                         const float* __restrict__ Wa, __half* __restrict__ wa,
                         const float* __restrict__ Wp, __half* __restrict__ wp)
{
    const int b = blockIdx.x;
    const int tid = threadIdx.x;
    if (b < 8192) {
        int idx = b * 256 + tid;
        float4 v = ((const float4*)x)[idx];
        *(uint32_t*)(xp + (size_t)idx * 4)     = pack_f16(v.x, v.y);
        *(uint32_t*)(xp + (size_t)idx * 4 + 2) = pack_f16(v.z, v.w);
    } else if (b < 8192 + 3072) {
        int bb = b - 8192;
        wt_block(Wa, wa, CC, 3 * CC, bb % 96, bb / 96, tid);
    } else {
        int bb = b - 11264;
        wt_block(Wp, wp, CC, CC, bb % 32, bb / 32, tid);
    }
}

// ---------------------------------------------------------------------------
// fp16 GEMM: C = A @ B^T + bias (single fp16 A and B).
// CTA 128x128, 4 warps (2x2), warp tile 64x64, K-chunk 64, 3-stage cp.async.
// Rows padded to 144B (128B data + 16 pad) -> conflict-free ldmatrix.
// MODE 0: fp32 row-major out. MODE 1: QKV epilogue (fp16 q/k/v outputs).
// ---------------------------------------------------------------------------
#define ROWB 144
#define TILE_B (128 * ROWB)           // 18432
#define NSTG 3
#define STAGE_B (2 * TILE_B)          // 36864 (A, B)
#define GEMM_SMEM (NSTG * STAGE_B)    // 110592

template <int MODE>
__global__ void __launch_bounds__(128, 2) mma_gemm(
    const __half* __restrict__ A_, const __half* __restrict__ B_,
    const float* __restrict__ bias,
    float* __restrict__ Cout,
    __half* __restrict__ Q_o, __half* __restrict__ K_o, __half* __restrict__ V_o,
    int N, int K)
{
    extern __shared__ char smg[];
    const uint32_t sbase = (uint32_t)__cvta_generic_to_shared(smg);
    const int tid = threadIdx.x;
    const int wid = tid >> 5, lane = tid & 31;
    const int wm = wid >> 1, wn = wid & 1;
    const int g = lane >> 2, tg = lane & 3;
    const int lrow = lane & 15, lhalf = lane >> 4;
    const int m0 = blockIdx.y * 128, n0 = blockIdx.x * 128;

    const __half* A = A_ + (size_t)m0 * K;
    const __half* B = B_ + (size_t)n0 * K;
    const __half* tp[2] = { A, B };

    const uint32_t aoff = (uint32_t)((wm * 64 + lrow) * ROWB + lhalf * 16);
    const uint32_t boff = (uint32_t)((wn * 64 + lrow) * ROWB + lhalf * 16) + TILE_B;

    float acc[4][8][4];
#pragma unroll
    for (int mt = 0; mt < 4; mt++)
#pragma unroll
        for (int nt = 0; nt < 8; nt++)
#pragma unroll
            for (int i = 0; i < 4; i++) acc[mt][nt][i] = 0.0f;

    // K-chunk 64: 2 tiles x 128 rows x 128B = 2048 x 16B ops, 16/thread
#define GEMM_ISSUE(chunk) do {                                                 \
    const uint32_t _sb = sbase + ((chunk) % NSTG) * STAGE_B;                   \
    const int _kc = (chunk) * 64;                                              \
    _Pragma("unroll")                                                          \
    for (int _i = 0; _i < 16; _i++) {                                          \
        int _e = _i * 128 + tid;                                               \
        int _t = _e >> 10, _r = (_e & 1023) >> 3, _h = _e & 7;                 \
        cp16(_sb + _t * TILE_B + _r * ROWB + _h * 16,                          \
             tp[_t] + (size_t)_r * K + _kc + _h * 8);                          \
    }                                                                          \
} while (0)

    const int NCH = K / 64;
    GEMM_ISSUE(0); cp_commit();
    GEMM_ISSUE(1); cp_commit();

    for (int c = 0; c < NCH; c++) {
        cp_wait1();
        __syncthreads();

        const uint32_t st = sbase + (c % NSTG) * STAGE_B;

#pragma unroll
        for (int ks = 0; ks < 4; ks++) {
            uint32_t ah[4][4];
#pragma unroll
            for (int mt = 0; mt < 4; mt++)
                ldsm4(ah[mt], st + aoff + mt * 16 * ROWB + ks * 32);
#pragma unroll
            for (int p = 0; p < 4; p++) {
                uint32_t rb[4];
                ldsm4(rb, st + boff + p * 16 * ROWB + ks * 32);
                uint32_t bE[2] = { rb[0], rb[2] }, bO[2] = { rb[1], rb[3] };
#pragma unroll
                for (int mt = 0; mt < 4; mt++) mma_f16(acc[mt][2 * p],     ah[mt], bE);
#pragma unroll
                for (int mt = 0; mt < 4; mt++) mma_f16(acc[mt][2 * p + 1], ah[mt], bO);
            }
        }

        if (c + 2 < NCH) GEMM_ISSUE(c + 2);
        cp_commit();   // empty group at tail keeps wait accounting uniform
    }
#undef GEMM_ISSUE

    // Epilogue
#pragma unroll
    for (int mt = 0; mt < 4; mt++) {
#pragma unroll
        for (int nt = 0; nt < 8; nt++) {
            const int cg = n0 + wn * 64 + nt * 8 + tg * 2;
            const int r0g = m0 + wm * 64 + mt * 16 + g;
            const float b0 = __ldg(bias + cg);
            const float b1 = __ldg(bias + cg + 1);
            float f00 = acc[mt][nt][0] + b0, f01 = acc[mt][nt][1] + b1;
            float f10 = acc[mt][nt][2] + b0, f11 = acc[mt][nt][3] + b1;
            if (MODE == 0) {
                *(float2*)(Cout + (size_t)r0g * N + cg) = make_float2(f00, f01);
                *(float2*)(Cout + (size_t)(r0g + 8) * N + cg) = make_float2(f10, f11);
            } else {
                const int which = cg >> 10;
                const int c10 = cg & 1023;
                const int h = c10 >> 6;
                const int d = c10 & 63;
                const int br = r0g >> 11, tr = r0g & 2047;
                const size_t i0 = ((((size_t)br * HH + h) * TT) + tr) * DD + d;
                if (which == 0) {
                    *(uint32_t*)(Q_o + i0)          = pack_f16(f00 * QSC, f01 * QSC);
                    *(uint32_t*)(Q_o + i0 + 8 * DD) = pack_f16(f10 * QSC, f11 * QSC);
                } else {
                    __half* base = (which == 1) ? K_o : V_o;
                    *(uint32_t*)(base + i0)          = pack_f16(f00, f01);
                    *(uint32_t*)(base + i0 + 8 * DD) = pack_f16(f10, f11);
                }
            }
        }
    }
}

// ---------------------------------------------------------------------------
// Flash attention (R12 config): fp16 mma (fp32 accum), 64-query tiles,
// 4 warps, V natural layout via ldmatrix.trans, 2-stage cp.async, 3 CTAs/SM.
// ---------------------------------------------------------------------------
#define ROWF 144
#define TILEF (64 * ROWF)   // 9216
#define FL_QH 0
#define FL_ST(s) (TILEF + (s) * 2 * TILEF)
#define FL_SMEM (5 * TILEF)  // 46080

__global__ void __launch_bounds__(128, 3) flash_mma(
    const __half* __restrict__ Qg,
    const __half* __restrict__ Kg, const __half* __restrict__ Vg,
    __half* __restrict__ at_o)
{
    extern __shared__ char smf[];
    const uint32_t sbase = (uint32_t)__cvta_generic_to_shared(smf);
    const int tid = threadIdx.x, wid = tid >> 5, lane = tid & 31;
    const int g = lane >> 2, tg = lane & 3;
    const int qt = 31 - blockIdx.x;
    const int bh = blockIdx.y;

    const __half* Qb = Qg + (size_t)bh * TT * DD;
    const __half* Kb = Kg + (size_t)bh * TT * DD;
    const __half* Vb = Vg + (size_t)bh * TT * DD;

    const int lrow = lane & 15, lhalf = lane >> 4;

#define ISSUE_KV(stg, kvi) do {                                                \
    const uint32_t _sb = sbase + FL_ST(stg);                                   \
    _Pragma("unroll")                                                          \
    for (int _i = 0; _i < 4; _i++) {                                           \
        int _ch = _i * 128 + tid;                                              \
        int _row = _ch >> 3, _c = _ch & 7;                                     \
        cp16(_sb + _row * ROWF + _c * 16,                                      \
             Kb + (size_t)(kvi) * 4096 + _ch * 8);                             \
        cp16(_sb + TILEF + _row * ROWF + _c * 16,                              \
             Vb + (size_t)(kvi) * 4096 + _ch * 8);                             \
    }                                                                          \
} while (0)

    // Prologue: Q tile (group 0), KV tile 0 (group 1)
#pragma unroll
    for (int i = 0; i < 4; i++) {
        int ch = i * 128 + tid;
        int row = ch >> 3, c = ch & 7;
        cp16(sbase + FL_QH + row * ROWF + c * 16, Qb + (size_t)qt * 4096 + ch * 8);
    }
    cp_commit();
    ISSUE_KV(0, 0);
    cp_commit();
    cp_wait1();
    __syncthreads();

    // Q fragments via ldmatrix (held for whole kernel)
    uint32_t qf[4][4];
    {
        const uint32_t qoff = sbase + (uint32_t)((wid * 16 + lrow) * ROWF + lhalf * 16);
#pragma unroll
        for (int j = 0; j < 4; j++) ldsm4(qf[j], qoff + FL_QH + j * 32);
    }

    float oacc[8][4];
#pragma unroll
    for (int i = 0; i < 8; i++)
#pragma unroll
        for (int jj = 0; jj < 4; jj++) oacc[i][jj] = 0.0f;
    float m0 = -1e30f, m1 = -1e30f, l0 = 0.0f, l1 = 0.0f;

    const uint32_t foff = (uint32_t)(lrow * ROWF + lhalf * 16);
    const uint32_t voff = (uint32_t)(((lane >> 4) * 8 + (lane & 7)) * ROWF
                                     + ((lane >> 3) & 1) * 16);

    for (int kv = 0; kv <= qt; kv++) {
        const int s = kv & 1;
        if (kv < qt) { ISSUE_KV(s ^ 1, kv + 1); cp_commit(); cp_wait1(); }
        else cp_wait0();
        __syncthreads();

        const uint32_t KHs = sbase + FL_ST(s) + foff;
        const uint32_t VHs = sbase + FL_ST(s) + TILEF + voff;

        // S = Q @ K^T  (fp32 accumulators)
        float sa[8][4];
#pragma unroll
        for (int nt = 0; nt < 8; nt++)
#pragma unroll
            for (int jj = 0; jj < 4; jj++) sa[nt][jj] = 0.0f;

#pragma unroll
        for (int j = 0; j < 4; j++) {
            uint32_t rk[4][4];
#pragma unroll
            for (int p = 0; p < 4; p++) ldsm4(rk[p], KHs + p * 16 * ROWF + j * 32);
#pragma unroll
            for (int p = 0; p < 4; p++) {
                uint32_t bE[2] = { rk[p][0], rk[p][2] }, bO[2] = { rk[p][1], rk[p][3] };
                mma_f16(sa[2 * p],     qf[j], bE);
                mma_f16(sa[2 * p + 1], qf[j], bO);
            }
        }

        // Causal mask (diagonal tile only)
        if (kv == qt) {
            const int r0 = wid * 16 + g, r1 = r0 + 8;
#pragma unroll
            for (int nt = 0; nt < 8; nt++) {
                int c0 = nt * 8 + tg * 2;
                if (c0 > r0)     sa[nt][0] = -1e30f;
                if (c0 + 1 > r0) sa[nt][1] = -1e30f;
                if (c0 > r1)     sa[nt][2] = -1e30f;
                if (c0 + 1 > r1) sa[nt][3] = -1e30f;
            }
        }

        // Online softmax (log2 domain)
        float mt0 = sa[0][0], mt1 = sa[0][2];
#pragma unroll
        for (int nt = 0; nt < 8; nt++) {
            mt0 = fmaxf(mt0, fmaxf(sa[nt][0], sa[nt][1]));
            mt1 = fmaxf(mt1, fmaxf(sa[nt][2], sa[nt][3]));
        }
        mt0 = fmaxf(mt0, __shfl_xor_sync(0xffffffffu, mt0, 1));
        mt0 = fmaxf(mt0, __shfl_xor_sync(0xffffffffu, mt0, 2));
        mt1 = fmaxf(mt1, __shfl_xor_sync(0xffffffffu, mt1, 1));
        mt1 = fmaxf(mt1, __shfl_xor_sync(0xffffffffu, mt1, 2));

        float mn0 = fmaxf(m0, mt0), mn1 = fmaxf(m1, mt1);
        float cr0 = ex2f(m0 - mn0), cr1 = ex2f(m1 - mn1);
        m0 = mn0; m1 = mn1;

        float s0 = 0.0f, s1 = 0.0f;
#pragma unroll
        for (int nt = 0; nt < 8; nt++) {
            sa[nt][0] = ex2f(sa[nt][0] - mn0);
            sa[nt][1] = ex2f(sa[nt][1] - mn0);
            sa[nt][2] = ex2f(sa[nt][2] - mn1);
            sa[nt][3] = ex2f(sa[nt][3] - mn1);
            s0 += sa[nt][0] + sa[nt][1];
            s1 += sa[nt][2] + sa[nt][3];
        }
        s0 += __shfl_xor_sync(0xffffffffu, s0, 1);
        s0 += __shfl_xor_sync(0xffffffffu, s0, 2);
        s1 += __shfl_xor_sync(0xffffffffu, s1, 1);
        s1 += __shfl_xor_sync(0xffffffffu, s1, 2);
        l0 = l0 * cr0 + s0;
        l1 = l1 * cr1 + s1;

#pragma unroll
        for (int nt = 0; nt < 8; nt++) {
            oacc[nt][0] *= cr0; oacc[nt][1] *= cr0;
            oacc[nt][2] *= cr1; oacc[nt][3] *= cr1;
        }

        // Pack P to fp16 A-fragments
        uint32_t pa[4][4];
#pragma unroll
        for (int j = 0; j < 4; j++) {
            pa[j][0] = pack_f16(sa[2 * j][0], sa[2 * j][1]);
            pa[j][1] = pack_f16(sa[2 * j][2], sa[2 * j][3]);
            pa[j][2] = pack_f16(sa[2 * j + 1][0], sa[2 * j + 1][1]);
            pa[j][3] = pack_f16(sa[2 * j + 1][2], sa[2 * j + 1][3]);
        }

        // O += P @ V  (V natural layout, trans ldmatrix; fp32 acc)
#pragma unroll
        for (int j = 0; j < 4; j++) {
            uint32_t rv[4][4];
#pragma unroll
            for (int p = 0; p < 4; p++)
                ldsm4t(rv[p], VHs + j * 16 * ROWF + p * 32);
#pragma unroll
            for (int p = 0; p < 4; p++) {
                uint32_t bE[2] = { rv[p][0], rv[p][2] }, bO[2] = { rv[p][1], rv[p][3] };
                mma_f16(oacc[2 * p],     pa[j], bE);
                mma_f16(oacc[2 * p + 1], pa[j], bO);
            }
        }
        __syncthreads();
    }

    // Epilogue: normalize, write att fp16 [M=B*T, C] (c = h*64+d)
    const float i0 = 1.0f / l0, i1 = 1.0f / l1;
    const int b = bh >> 4, h = bh & 15;
    const int t0 = qt * 64 + wid * 16 + g;
    const size_t row0 = ((size_t)b * TT + t0) * CC + h * DD;
    const size_t row1 = row0 + (size_t)8 * CC;
#pragma unroll
    for (int nt = 0; nt < 8; nt++) {
        const int d = nt * 8 + tg * 2;
        *(uint32_t*)(at_o + row0 + d) = pack_f16(oacc[nt][0] * i0, oacc[nt][1] * i0);
        *(uint32_t*)(at_o + row1 + d) = pack_f16(oacc[nt][2] * i1, oacc[nt][3] * i1);
    }
#undef ISSUE_KV
}

// ---------------------------------------------------------------------------
extern "C" void kernel_launch(void* const* d_in, const int* in_sizes, int n_in,
                              void* d_out, int out_size)
{
    (void)in_sizes; (void)n_in; (void)out_size;
    const float* x      = (const float*)d_in[0];
    const float* W_attn = (const float*)d_in[1];
    const float* b_attn = (const float*)d_in[2];
    const float* W_proj = (const float*)d_in[3];
    const float* b_proj = (const float*)d_in[4];
    float* out = (float*)d_out;

    __half *xp, *wa, *wp, *at, *q, *k, *v;
    cudaGetSymbolAddress((void**)&xp, g_x);
    cudaGetSymbolAddress((void**)&wa, g_wa);
    cudaGetSymbolAddress((void**)&wp, g_wp);
    cudaGetSymbolAddress((void**)&at, g_at);
    cudaGetSymbolAddress((void**)&q, g_q);
    cudaGetSymbolAddress((void**)&k, g_k);
    cudaGetSymbolAddress((void**)&v, g_v);

    cudaFuncSetAttribute((const void*)mma_gemm<1>,
                         cudaFuncAttributeMaxDynamicSharedMemorySize, GEMM_SMEM);
    cudaFuncSetAttribute((const void*)mma_gemm<0>,
                         cudaFuncAttributeMaxDynamicSharedMemorySize, GEMM_SMEM);
    cudaFuncSetAttribute((const void*)flash_mma,
                         cudaFuncAttributeMaxDynamicSharedMemorySize, FL_SMEM);

    // 1) Fused prep: x convert + both weight transposes in one launch
    prep_all<<<12288, 256>>>(x, xp, W_attn, wa, W_proj, wp);

    // 2) QKV GEMM -> q (scaled), k, v — all single fp16, [B,H,T,D]
    mma_gemm<1><<<dim3(3 * CC / 128, MROWS / 128), 128, GEMM_SMEM>>>(
        xp, wa, b_attn, nullptr, q, k, v, 3 * CC, CC);

    // 3) Flash attention (64-query tiles, 3 CTAs/SM) -> att fp16
    flash_mma<<<dim3(TT / 64, BB * HH), 128, FL_SMEM>>>(q, k, v, at);

    // 4) Projection GEMM -> out (fp32)
    mma_gemm<0><<<dim3(CC / 128, MROWS / 128), 128, GEMM_SMEM>>>(
        at, wp, b_proj, out, nullptr, nullptr, nullptr, CC, CC);
}